// round 13
// baseline (speedup 1.0000x reference)
#include <cuda_runtime.h>

#define MODES 64
#define AUD   16
#define T     32768
#define F     4096
#define NC    513
#define NB    128
#define NT    1024

typedef unsigned long long u64;

__device__ __forceinline__ u64 fma2(u64 a, u64 b, u64 c) {
    u64 d; asm("fma.rn.f32x2 %0, %1, %2, %3;" : "=l"(d) : "l"(a), "l"(b), "l"(c)); return d;
}
__device__ __forceinline__ u64 add2(u64 a, u64 b) {
    u64 d; asm("add.rn.f32x2 %0, %1, %2;" : "=l"(d) : "l"(a), "l"(b)); return d;
}
__device__ __forceinline__ u64 pack2(float x, float y) {
    u64 d; asm("mov.b64 %0, {%1, %2};" : "=l"(d) : "f"(x), "f"(y)); return d;
}
__device__ __forceinline__ float2 unpack2(u64 v) {
    float2 r; asm("mov.b64 {%0, %1}, %2;" : "=f"(r.x), "=f"(r.y) : "l"(v)); return r;
}

// ---------------- device scratch ----------------
__device__ float2 g_Fd[MODES * 64];    // e^{-d r}  * (sin, cos)(w r)
__device__ float2 g_Cd[MODES * NC];    // e^{-d 64c}* (sin, cos)(w 64c)
__device__ float  g_ampT[MODES * AUD];
__device__ float2 g_cum2[2][8][MODES * AUD];  // per-taphalf lag-chunk prefix
__device__ float  g_dpart[AUD * F];
__device__ unsigned g_cntA = 0, g_genA = 0;   // all 128 blocks
__device__ unsigned g_cntB = 0, g_genB = 0;   // blocks 0..63 only

__device__ __forceinline__ void bar_sync(unsigned* cnt, unsigned* gen, unsigned target)
{
    __threadfence();
    __syncthreads();
    if (threadIdx.x == 0) {
        unsigned g = *(volatile unsigned*)gen;
        __threadfence();
        if (atomicAdd(cnt, 1u) == target - 1) {
            *cnt = 0;
            __threadfence();
            *(volatile unsigned*)gen = g + 1;
        } else {
            while (*(volatile unsigned*)gen == g) { }
        }
        __threadfence();
    }
    __syncthreads();
}

// ---------------- shared param computation (alpha/beta -> d, w into sm[off],sm[off+1]) ----------------
__device__ __forceinline__ void mode_params(int m, float* sp,
                                            const float* freq_linear,
                                            const float* alpha_params,
                                            const float* beta_params)
{
    int tid = threadIdx.x;
    const float la0 = logf(0.6f), la1 = logf(60.0f);
    const float lb0 = logf(2e-8f), lb1 = logf(2e-6f);
    if (tid < 64) {
        float frac = (float)tid / 63.0f;
        float va = expf(la0 + (la1 - la0) * frac);
        float vb = expf(lb0 + (lb1 - lb0) * frac);
        float spa = log1pf(expf(alpha_params[m * 64 + tid]));
        float spb = log1pf(expf(beta_params [m * 64 + tid]));
        sp[tid]       = spa * va;  sp[64 + tid]  = spa;
        sp[128 + tid] = spb * vb;  sp[192 + tid] = spb;
    }
    __syncthreads();
    if (tid < 32) {
        float A  = sp[tid]       + sp[tid + 32];
        float AW = sp[64 + tid]  + sp[96 + tid];
        float Bv = sp[128 + tid] + sp[160 + tid];
        float BW = sp[192 + tid] + sp[224 + tid];
        #pragma unroll
        for (int o = 16; o; o >>= 1) {
            A  += __shfl_xor_sync(0xffffffffu, A, o);
            AW += __shfl_xor_sync(0xffffffffu, AW, o);
            Bv += __shfl_xor_sync(0xffffffffu, Bv, o);
            BW += __shfl_xor_sync(0xffffffffu, BW, o);
        }
        if (tid == 0) {
            float alpha = A / AW, beta = Bv / BW;
            float f2pi = freq_linear[m] * 6.28318530717958647692f;
            float lbd  = f2pi * f2pi;
            float dr   = 0.5f * (alpha + beta * lbd);
            sp[256] = dr / 16000.0f;
            sp[257] = sqrtf(lbd - dr * dr) / 16000.0f;
        }
    }
    __syncthreads();
}

__global__ void __launch_bounds__(NT) k_all(const float* __restrict__ freq_linear,
                                            const float* __restrict__ amp_value,
                                            const float* __restrict__ alpha_params,
                                            const float* __restrict__ beta_params,
                                            const float* __restrict__ forces,
                                            float* __restrict__ out)
{
    __shared__ __align__(16) float sm[6912];   // 27KB
    int b = blockIdx.x, tid = threadIdx.x;

    if (b < 64) {
        // ============ Stage 1a: decay tables for mode b ============
        int m = b;
        mode_params(m, sm, freq_linear, alpha_params, beta_params);
        float d = sm[256], w = sm[257];
        if (tid < 16) {
            float x = amp_value[tid * MODES + m];
            float s = 1.0f / (1.0f + expf(-x));
            g_ampT[m * AUD + tid] = 2.0f * expf(2.30258509299404568f * logf(s)) + 1e-7f;
        } else if (tid >= 64 && tid < 577) {
            int i = tid - 64;
            float n = (float)(i << 6);
            float s, c;
            sincosf(w * n, &s, &c);
            float Ec = expf(-d * n);
            g_Cd[m * NC + i] = make_float2(Ec * s, Ec * c);
        } else if (tid >= 577 && tid < 641) {
            int i = tid - 577;
            float nf = (float)i;
            float s, c;
            sincosf(w * nf, &s, &c);
            float Ef = expf(-d * nf);
            g_Fd[m * 64 + i] = make_float2(Ef * s, Ef * c);
        }

        bar_sync(&g_cntA, &g_genA, NB);

        // ============ Stage 2a: diagonal conv (unit b) ============
        {
            int ti = b >> 3, p = b & 7;
            int a0 = 2 * p, a1 = a0 + 1;
            u64* sfr2 = (u64*)sm;          // 512
            u64* sp2  = sfr2 + 512;        // 1024
            u64* spb  = sfr2 + 1536;       // 512
            u64* sam2 = sfr2 + 2048;       // 64
            int fb = 3584 - (ti << 9);

            __syncthreads();
            if (tid < 512) {
                sfr2[tid] = pack2(forces[a0 * F + fb + tid], forces[a1 * F + fb + tid]);
            } else {
                int i = tid - 512;
                if (i < 511)  sp2[i] = 0ull;
                if (i == 511) sp2[1023] = 0ull;
                if (i < 64)   sam2[i] = pack2(g_ampT[i * AUD + a0], g_ampT[i * AUD + a1]);
            }
            __syncthreads();

            {
                int j = tid & 511;
                int mlo = (tid >> 9) << 5;
                int n = j + 1, c2 = n >> 6, r2 = n & 63;
                u64 v2 = 0ull;
                #pragma unroll 4
                for (int mm = 0; mm < 32; mm++) {
                    int mo = mlo + mm;
                    float2 Fd = g_Fd[mo * 64 + r2];
                    float2 Cd = g_Cd[mo * NC + c2];
                    float ps = Cd.x * Fd.y + Cd.y * Fd.x;
                    v2 = fma2(pack2(ps, ps), sam2[mo], v2);
                }
                if (tid < 512) sp2[511 + j] = v2;
                else           spb[j] = v2;
            }
            __syncthreads();
            if (tid < 512) sp2[511 + tid] = add2(sp2[511 + tid], spb[tid]);
            __syncthreads();

            {
                int u  = tid & 511;
                int k0 = (tid >> 9) << 8;
                u64 ae = 0ull, ao = 0ull;
                #pragma unroll 8
                for (int k = k0; k < k0 + 256; k += 2) {
                    ae = fma2(sfr2[k],     sp2[u + k],     ae);
                    ao = fma2(sfr2[k + 1], sp2[u + k + 1], ao);
                }
                u64 acc = add2(ae, ao);
                if (tid < 512) spb[u] = acc;
                __syncthreads();
                if (tid >= 512) {
                    float2 r = unpack2(add2(acc, spb[u]));
                    int t0 = (ti << 9) + u;
                    g_dpart[a0 * F + t0] = r.x;
                    g_dpart[a1 * F + t0] = r.y;
                }
            }
        }

        bar_sync(&g_cntB, &g_genB, 64);
        // fall through to phase C with tile = b (0..63)
    } else {
        // ============ Stage 1b: self-contained mode-dot for mode b-64 ============
        int m = b - 64;
        mode_params(m, sm + 1536, freq_linear, alpha_params, beta_params);
        float d = sm[1536 + 256], w = sm[1536 + 257];

        u64*    sR  = (u64*)sm;                    // floats [0..1023]
        float2* sFg = (float2*)(sm + 1024);        // 64
        float2* sCg = (float2*)(sm + 1152);        // 64
        float*  sam = sm + 1280;                   // 16

        if (tid < 64) {
            float nf = (float)tid;
            float s, c;
            sincosf(w * nf, &s, &c);
            float Ep = expf(d * nf);
            sFg[tid] = make_float2(Ep * s, Ep * c);
        } else if (tid < 128) {
            int i = tid - 64;
            float n = (float)(i << 6);
            float s, c;
            sincosf(w * n, &s, &c);
            float Ecp = expf(d * n);
            sCg[i] = make_float2(Ecp * s, Ecp * c);
        } else if (tid < 144) {
            int a = tid - 128;
            float x = amp_value[a * MODES + m];
            float s = 1.0f / (1.0f + expf(-x));
            sam[a] = 2.0f * expf(2.30258509299404568f * logf(s)) + 1e-7f;
        }
        __syncthreads();

        int wid = tid >> 5, lane = tid & 31;
        int a = wid >> 1, half = wid & 1;
        float am = sam[a];
        float pA = 0.f, pB = 0.f;

        for (int c = 0; c < 8; c++) {
            int k0 = c << 9;
            __syncthreads();
            if (tid < 512) {
                int tau = k0 + tid;
                float2 Fg = sFg[tau & 63];
                float2 Cg = sCg[tau >> 6];
                sR[tid] = pack2(Cg.y * Fg.y - Cg.x * Fg.x,
                                Cg.x * Fg.y + Cg.y * Fg.x);
            }
            __syncthreads();
            const float* f0 = forces + a * F + 4095 - k0;
            u64 AB = 0ull;
            #pragma unroll 8
            for (int s = 0; s < 8; s++) {
                int k = (half << 8) + lane + (s << 5);
                float fv = f0[-k];
                AB = fma2(pack2(fv, fv), sR[k], AB);
            }
            float2 ab = unpack2(AB);
            float A = ab.x, B = ab.y;
            #pragma unroll
            for (int o = 16; o; o >>= 1) {
                A += __shfl_xor_sync(0xffffffffu, A, o);
                B += __shfl_xor_sync(0xffffffffu, B, o);
            }
            pA += A; pB += B;
            if (lane == 0)
                g_cum2[half][c][m * AUD + a] = make_float2(am * pA, am * pB);
        }

        bar_sync(&g_cntA, &g_genA, NB);
        // fall through to phase C with tile = b (64..127) — no dpart needed
    }

    // ================= Phase C: 256-sample tile = b, 4 groups (2 audio x 2 mode halves) =================
    {
        int tile = b;
        int tl = tid & 255, g = tid >> 8;
        int ag = g & 1, mg = g >> 1;
        int t = tile * 256 + tl;
        int cc = tile >> 1; if (cc > 8) cc = 8;

        u64*    sA   = (u64*)sm;                // 512
        u64*    sB   = sA + 512;                // 512
        float2* sCd  = (float2*)(sA + 1024);    // 320
        u64*    comb = sA + 1344;               // 2048

        u64 acc2[4] = {0ull, 0ull, 0ull, 0ull};
        __syncthreads();

        if (cc > 0) {
            int c2base = (tile * 256 + 1) >> 6;
            if (tid < 512) {
                int mm = tid >> 3, aa = tid & 7;
                float2 h00 = g_cum2[0][cc - 1][mm * AUD + 2 * aa];
                float2 h10 = g_cum2[1][cc - 1][mm * AUD + 2 * aa];
                float2 h01 = g_cum2[0][cc - 1][mm * AUD + 2 * aa + 1];
                float2 h11 = g_cum2[1][cc - 1][mm * AUD + 2 * aa + 1];
                sA[tid] = pack2(h00.x + h10.x, h01.x + h11.x);
                sB[tid] = pack2(h00.y + h10.y, h01.y + h11.y);
            } else if (tid < 832) {
                int idx = tid - 512;
                int mm = idx / 5, dc = idx % 5;
                sCd[mm * 5 + dc] = g_Cd[mm * NC + c2base + dc];
            }
            __syncthreads();

            int n = t + 1, dc = (n >> 6) - c2base, r2 = n & 63;
            int mbase = mg << 5;
            #pragma unroll 4
            for (int mm = 0; mm < 32; mm++) {
                int m = mbase + mm;
                float2 Fd = g_Fd[m * 64 + r2];
                float2 Cd = sCd[m * 5 + dc];
                float ps  = Cd.x * Fd.y + Cd.y * Fd.x;
                float npc = Cd.x * Fd.x - Cd.y * Fd.y;
                u64 ps2  = pack2(ps, ps);
                u64 npc2 = pack2(npc, npc);
                const ulonglong2* pAv = (const ulonglong2*)(sA + m * 8 + ag * 4);
                const ulonglong2* pBv = (const ulonglong2*)(sB + m * 8 + ag * 4);
                ulonglong2 va0 = pAv[0], vb0 = pBv[0];
                ulonglong2 va1 = pAv[1], vb1 = pBv[1];
                acc2[0] = fma2(ps2, va0.x, fma2(npc2, vb0.x, acc2[0]));
                acc2[1] = fma2(ps2, va0.y, fma2(npc2, vb0.y, acc2[1]));
                acc2[2] = fma2(ps2, va1.x, fma2(npc2, vb1.x, acc2[2]));
                acc2[3] = fma2(ps2, va1.y, fma2(npc2, vb1.y, acc2[3]));
            }
        }
        __syncthreads();
        if (mg == 1) {
            u64* cp = comb + ((ag << 8) + tl) * 4;
            cp[0] = acc2[0]; cp[1] = acc2[1]; cp[2] = acc2[2]; cp[3] = acc2[3];
        }
        __syncthreads();
        if (mg == 0) {
            u64* cp = comb + ((ag << 8) + tl) * 4;
            float o[8];
            #pragma unroll
            for (int j = 0; j < 4; j++) {
                float2 v = unpack2(add2(acc2[j], cp[j]));
                o[2 * j] = v.x; o[2 * j + 1] = v.y;
            }
            int abase = ag << 3;
            if (t < F) {
                #pragma unroll
                for (int j = 0; j < 8; j++)
                    o[j] += g_dpart[(abase + j) * F + t];
            }
            #pragma unroll
            for (int j = 0; j < 8; j++)
                out[(abase + j) * T + t] = o[j];
        }
    }
}

// ---------------- launch ----------------
extern "C" void kernel_launch(void* const* d_in, const int* in_sizes, int n_in,
                              void* d_out, int out_size)
{
    const float* freq   = (const float*)d_in[0];
    const float* ampv   = (const float*)d_in[1];
    const float* ap     = (const float*)d_in[2];
    const float* bp     = (const float*)d_in[3];
    const float* forces = (const float*)d_in[4];
    float* out = (float*)d_out;

    k_all<<<NB, NT>>>(freq, ampv, ap, bp, forces, out);
}

// round 14
// speedup vs baseline: 1.1485x; 1.1485x over previous
#include <cuda_runtime.h>

#define MODES 64
#define AUD   16
#define T     32768
#define F     4096
#define NC    513
#define NB    128
#define NT    1024

typedef unsigned long long u64;

__device__ __forceinline__ u64 fma2(u64 a, u64 b, u64 c) {
    u64 d; asm("fma.rn.f32x2 %0, %1, %2, %3;" : "=l"(d) : "l"(a), "l"(b), "l"(c)); return d;
}
__device__ __forceinline__ u64 add2(u64 a, u64 b) {
    u64 d; asm("add.rn.f32x2 %0, %1, %2;" : "=l"(d) : "l"(a), "l"(b)); return d;
}
__device__ __forceinline__ u64 pack2(float x, float y) {
    u64 d; asm("mov.b64 %0, {%1, %2};" : "=l"(d) : "f"(x), "f"(y)); return d;
}
__device__ __forceinline__ float2 unpack2(u64 v) {
    float2 r; asm("mov.b64 {%0, %1}, %2;" : "=f"(r.x), "=f"(r.y) : "l"(v)); return r;
}

// ---------------- device scratch ----------------
__device__ float2 g_Fd[MODES * 64];    // e^{-d r}  * (sin, cos)(w r)
__device__ float2 g_Cd[MODES * NC];    // e^{-d 64c}* (sin, cos)(w 64c)
__device__ float2 g_Fg[MODES * 64];    // e^{+d r}  * (sin, cos)
__device__ float2 g_Cg[MODES * 64];    // e^{+d 64c}* (sin, cos)
__device__ float  g_ampT[MODES * AUD];
__device__ float2 g_dots[8][MODES * AUD];   // RAW amp-scaled lag-chunk dots
__device__ float  g_dpart[AUD * F];
__device__ unsigned g_count = 0;
__device__ unsigned g_gen   = 0;

__device__ __forceinline__ void grid_bar()
{
    __threadfence();
    __syncthreads();
    if (threadIdx.x == 0) {
        unsigned gen = *(volatile unsigned*)&g_gen;
        __threadfence();
        if (atomicAdd(&g_count, 1u) == NB - 1) {
            g_count = 0;
            __threadfence();
            *(volatile unsigned*)&g_gen = gen + 1;
        } else {
            while (*(volatile unsigned*)&g_gen == gen) { }
        }
        __threadfence();
    }
    __syncthreads();
}

__global__ void __launch_bounds__(NT) k_all(const float* __restrict__ freq_linear,
                                            const float* __restrict__ amp_value,
                                            const float* __restrict__ alpha_params,
                                            const float* __restrict__ beta_params,
                                            const float* __restrict__ forces,
                                            float* __restrict__ out)
{
    __shared__ __align__(16) u64 smu[4224];   // 33.8KB, re-carved per phase
    float* sm = (float*)smu;
    int b = blockIdx.x, tid = threadIdx.x;

    // ================= Phase A: 2 blocks per mode =================
    {
        int m = b & 63, half = b >> 6;
        float* s_a  = sm;        float* s_aw = sm + 64;
        float* s_b  = sm + 128;  float* s_bw = sm + 192;

        const float la0 = logf(0.6f), la1 = logf(60.0f);
        const float lb0 = logf(2e-8f), lb1 = logf(2e-6f);

        if (tid < 64) {
            float frac = (float)tid / 63.0f;
            float va = expf(la0 + (la1 - la0) * frac);
            float vb = expf(lb0 + (lb1 - lb0) * frac);
            float spa = log1pf(expf(alpha_params[m * 64 + tid]));
            float spb = log1pf(expf(beta_params [m * 64 + tid]));
            s_a[tid] = spa * va; s_aw[tid] = spa;
            s_b[tid] = spb * vb; s_bw[tid] = spb;
        } else if (half == 0 && tid < 80) {
            int a = tid - 64;
            float x = amp_value[a * MODES + m];
            float s = 1.0f / (1.0f + expf(-x));
            g_ampT[m * AUD + a] = 2.0f * expf(2.30258509299404568f * logf(s)) + 1e-7f;
        }
        __syncthreads();
        if (tid < 32) {
            float A  = s_a[tid]  + s_a[tid + 32];
            float AW = s_aw[tid] + s_aw[tid + 32];
            float Bv = s_b[tid]  + s_b[tid + 32];
            float BW = s_bw[tid] + s_bw[tid + 32];
            #pragma unroll
            for (int o = 16; o; o >>= 1) {
                A  += __shfl_xor_sync(0xffffffffu, A, o);
                AW += __shfl_xor_sync(0xffffffffu, AW, o);
                Bv += __shfl_xor_sync(0xffffffffu, Bv, o);
                BW += __shfl_xor_sync(0xffffffffu, BW, o);
            }
            if (tid == 0) {
                float alpha = A / AW, beta = Bv / BW;
                float f2pi = freq_linear[m] * 6.28318530717958647692f;
                float lbd  = f2pi * f2pi;
                float dr   = 0.5f * (alpha + beta * lbd);
                sm[256] = dr / 16000.0f;
                sm[257] = sqrtf(lbd - dr * dr) / 16000.0f;
            }
        }
        __syncthreads();
        float d = sm[256], w = sm[257];
        if (half == 0) {
            if (tid < 257) {
                float n = (float)(tid << 6);
                float s, c;
                sincosf(w * n, &s, &c);
                float Ec = expf(-d * n);
                g_Cd[m * NC + tid] = make_float2(Ec * s, Ec * c);
            }
            if (tid < 64) {
                float nf = (float)tid;
                float s, c;
                sincosf(w * nf, &s, &c);
                float Ef = expf(-d * nf), Ep = expf(d * nf);
                g_Fd[m * 64 + tid] = make_float2(Ef * s, Ef * c);
                g_Fg[m * 64 + tid] = make_float2(Ep * s, Ep * c);
                float nc2 = (float)(tid << 6);
                float s2, c2;
                sincosf(w * nc2, &s2, &c2);
                float Ecp = expf(d * nc2);
                g_Cg[m * 64 + tid] = make_float2(Ecp * s2, Ecp * c2);
            }
        } else {
            if (tid < 256) {
                int i = 257 + tid;
                float n = (float)(i << 6);
                float s, c;
                sincosf(w * n, &s, &c);
                float Ec = expf(-d * n);
                g_Cd[m * NC + i] = make_float2(Ec * s, Ec * c);
            }
        }
    }

    grid_bar();

    // ================= Phase B =================
    if (b < 64) {
        // diag pair (ti = b>>3, audio pair p = b&7)
        int ti = b >> 3, p = b & 7;
        int a0 = 2 * p, a1 = a0 + 1;
        u64* sfr2 = smu;               // 512
        u64* sp2  = sfr2 + 512;        // 1024
        u64* spb  = sfr2 + 1536;       // 512
        u64* sam2 = sfr2 + 2048;       // 64
        int fb = 3584 - (ti << 9);

        if (tid < 512) {
            sfr2[tid] = pack2(forces[a0 * F + fb + tid], forces[a1 * F + fb + tid]);
        } else {
            int i = tid - 512;
            if (i < 511)  sp2[i] = 0ull;
            if (i == 511) sp2[1023] = 0ull;
            if (i < 64)   sam2[i] = pack2(g_ampT[i * AUD + a0], g_ampT[i * AUD + a1]);
        }
        __syncthreads();

        // s0: mode-split halves
        {
            int j = tid & 511;
            int mlo = (tid >> 9) << 5;        // 0 or 32
            int n = j + 1, c2 = n >> 6, r2 = n & 63;
            u64 v2 = 0ull;
            #pragma unroll 4
            for (int mm = 0; mm < 32; mm++) {
                int m = mlo + mm;
                float2 Fd = g_Fd[m * 64 + r2];
                float2 Cd = g_Cd[m * NC + c2];
                float ps = Cd.x * Fd.y + Cd.y * Fd.x;
                v2 = fma2(pack2(ps, ps), sam2[m], v2);
            }
            if (tid < 512) sp2[511 + j] = v2;
            else           spb[j] = v2;
        }
        __syncthreads();
        if (tid < 512) sp2[511 + tid] = add2(sp2[511 + tid], spb[tid]);
        __syncthreads();

        // conv: tap-split halves
        {
            int u  = tid & 511;
            int k0 = (tid >> 9) << 8;         // 0 or 256
            u64 ae = 0ull, ao = 0ull;
            #pragma unroll 8
            for (int k = k0; k < k0 + 256; k += 2) {
                ae = fma2(sfr2[k],     sp2[u + k],     ae);
                ao = fma2(sfr2[k + 1], sp2[u + k + 1], ao);
            }
            u64 acc = add2(ae, ao);
            if (tid < 512) spb[u] = acc;
            __syncthreads();
            if (tid >= 512) {
                float2 r = unpack2(add2(acc, spb[u]));
                int t0 = (ti << 9) + u;
                g_dpart[a0 * F + t0] = r.x;
                g_dpart[a1 * F + t0] = r.y;
            }
        }
    } else {
        // ---- one mode per block: ALL 128 (audio x chunk) dot units concurrently ----
        int m = b - 64;
        u64* sR = smu;                 // 4096 taps of (rc, rs)
        int wid = tid >> 5, lane = tid & 31;
        int a = wid >> 1, h = wid & 1;     // warp owns audio a, chunks 4h..4h+3
        float am = g_ampT[m * AUD + a];

        for (int i = tid; i < 4096; i += NT) {
            float2 Fg = g_Fg[m * 64 + (i & 63)];
            float2 Cg = g_Cg[m * 64 + (i >> 6)];
            sR[i] = pack2(Cg.y * Fg.y - Cg.x * Fg.x,
                          Cg.x * Fg.y + Cg.y * Fg.x);
        }
        __syncthreads();

        const float* fp = forces + a * F + 4095;   // g[tau] = fp[-tau]
        u64 acc0 = 0ull, acc1 = 0ull, acc2 = 0ull, acc3 = 0ull;
        int kb = (h << 2) << 9;                    // chunk base: 0 or 2048
        #pragma unroll 4
        for (int s = 0; s < 16; s++) {
            int k = kb + lane + (s << 5);
            float f0 = fp[-k];
            float f1 = fp[-(k + 512)];
            float f2 = fp[-(k + 1024)];
            float f3 = fp[-(k + 1536)];
            acc0 = fma2(pack2(f0, f0), sR[k],        acc0);
            acc1 = fma2(pack2(f1, f1), sR[k + 512],  acc1);
            acc2 = fma2(pack2(f2, f2), sR[k + 1024], acc2);
            acc3 = fma2(pack2(f3, f3), sR[k + 1536], acc3);
        }
        float2 d0 = unpack2(acc0), d1 = unpack2(acc1), d2 = unpack2(acc2), d3 = unpack2(acc3);
        #pragma unroll
        for (int o = 16; o; o >>= 1) {
            d0.x += __shfl_xor_sync(0xffffffffu, d0.x, o);
            d0.y += __shfl_xor_sync(0xffffffffu, d0.y, o);
            d1.x += __shfl_xor_sync(0xffffffffu, d1.x, o);
            d1.y += __shfl_xor_sync(0xffffffffu, d1.y, o);
            d2.x += __shfl_xor_sync(0xffffffffu, d2.x, o);
            d2.y += __shfl_xor_sync(0xffffffffu, d2.y, o);
            d3.x += __shfl_xor_sync(0xffffffffu, d3.x, o);
            d3.y += __shfl_xor_sync(0xffffffffu, d3.y, o);
        }
        if (lane == 0) {
            int cb = h << 2;
            g_dots[cb + 0][m * AUD + a] = make_float2(am * d0.x, am * d0.y);
            g_dots[cb + 1][m * AUD + a] = make_float2(am * d1.x, am * d1.y);
            g_dots[cb + 2][m * AUD + a] = make_float2(am * d2.x, am * d2.y);
            g_dots[cb + 3][m * AUD + a] = make_float2(am * d3.x, am * d3.y);
        }
    }

    grid_bar();

    // ================= Phase C: 256-sample tile, 4 groups (2 audio x 2 mode halves) =================
    {
        int tile = b;
        int tl = tid & 255, g = tid >> 8;
        int ag = g & 1, mg = g >> 1;
        int t = tile * 256 + tl;
        int cc = tile >> 1; if (cc > 8) cc = 8;

        u64*    sA   = smu;                     // 512
        u64*    sB   = sA + 512;                // 512
        float2* sCd  = (float2*)(sA + 1024);    // 320
        u64*    comb = sA + 1344;               // 2048

        u64 acc2[4] = {0ull, 0ull, 0ull, 0ull};

        if (cc > 0) {
            int c2base = (tile * 256 + 1) >> 6;
            if (tid < 512) {
                int mm = tid >> 3, aa = tid & 7;
                int i0 = mm * AUD + 2 * aa;
                float Ae = 0.f, Be = 0.f, Ao = 0.f, Bo = 0.f;
                for (int c = 0; c < cc; c++) {
                    float2 p0 = g_dots[c][i0];
                    float2 p1 = g_dots[c][i0 + 1];
                    Ae += p0.x; Be += p0.y;
                    Ao += p1.x; Bo += p1.y;
                }
                sA[tid] = pack2(Ae, Ao);
                sB[tid] = pack2(Be, Bo);
            } else if (tid < 832) {
                int idx = tid - 512;
                int mm = idx / 5, dc = idx % 5;
                sCd[mm * 5 + dc] = g_Cd[mm * NC + c2base + dc];
            }
            __syncthreads();

            int n = t + 1, dc = (n >> 6) - c2base, r2 = n & 63;
            int mbase = mg << 5;
            #pragma unroll 4
            for (int mm = 0; mm < 32; mm++) {
                int m = mbase + mm;
                float2 Fd = g_Fd[m * 64 + r2];
                float2 Cd = sCd[m * 5 + dc];
                float ps  = Cd.x * Fd.y + Cd.y * Fd.x;
                float npc = Cd.x * Fd.x - Cd.y * Fd.y;
                u64 ps2  = pack2(ps, ps);
                u64 npc2 = pack2(npc, npc);
                const ulonglong2* pAv = (const ulonglong2*)(sA + m * 8 + ag * 4);
                const ulonglong2* pBv = (const ulonglong2*)(sB + m * 8 + ag * 4);
                ulonglong2 va0 = pAv[0], vb0 = pBv[0];
                ulonglong2 va1 = pAv[1], vb1 = pBv[1];
                acc2[0] = fma2(ps2, va0.x, fma2(npc2, vb0.x, acc2[0]));
                acc2[1] = fma2(ps2, va0.y, fma2(npc2, vb0.y, acc2[1]));
                acc2[2] = fma2(ps2, va1.x, fma2(npc2, vb1.x, acc2[2]));
                acc2[3] = fma2(ps2, va1.y, fma2(npc2, vb1.y, acc2[3]));
            }
        }
        __syncthreads();
        if (mg == 1) {
            u64* cp = comb + ((ag << 8) + tl) * 4;
            cp[0] = acc2[0]; cp[1] = acc2[1]; cp[2] = acc2[2]; cp[3] = acc2[3];
        }
        __syncthreads();
        if (mg == 0) {
            u64* cp = comb + ((ag << 8) + tl) * 4;
            float o[8];
            #pragma unroll
            for (int j = 0; j < 4; j++) {
                float2 v = unpack2(add2(acc2[j], cp[j]));
                o[2 * j] = v.x; o[2 * j + 1] = v.y;
            }
            int abase = ag << 3;
            if (t < F) {
                #pragma unroll
                for (int j = 0; j < 8; j++)
                    o[j] += g_dpart[(abase + j) * F + t];
            }
            #pragma unroll
            for (int j = 0; j < 8; j++)
                out[(abase + j) * T + t] = o[j];
        }
    }
}

// ---------------- launch ----------------
extern "C" void kernel_launch(void* const* d_in, const int* in_sizes, int n_in,
                              void* d_out, int out_size)
{
    const float* freq   = (const float*)d_in[0];
    const float* ampv   = (const float*)d_in[1];
    const float* ap     = (const float*)d_in[2];
    const float* bp     = (const float*)d_in[3];
    const float* forces = (const float*)d_in[4];
    float* out = (float*)d_out;

    k_all<<<NB, NT>>>(freq, ampv, ap, bp, forces, out);
}

// round 15
// speedup vs baseline: 1.4194x; 1.2359x over previous
#include <cuda_runtime.h>

#define MODES 64
#define AUD   16
#define T     32768
#define F     4096
#define NC    513
#define NB    128
#define NT    1024

typedef unsigned long long u64;

__device__ __forceinline__ u64 fma2(u64 a, u64 b, u64 c) {
    u64 d; asm("fma.rn.f32x2 %0, %1, %2, %3;" : "=l"(d) : "l"(a), "l"(b), "l"(c)); return d;
}
__device__ __forceinline__ u64 add2(u64 a, u64 b) {
    u64 d; asm("add.rn.f32x2 %0, %1, %2;" : "=l"(d) : "l"(a), "l"(b)); return d;
}
__device__ __forceinline__ u64 pack2(float x, float y) {
    u64 d; asm("mov.b64 %0, {%1, %2};" : "=l"(d) : "f"(x), "f"(y)); return d;
}
__device__ __forceinline__ float2 unpack2(u64 v) {
    float2 r; asm("mov.b64 {%0, %1}, %2;" : "=f"(r.x), "=f"(r.y) : "l"(v)); return r;
}

// ---------------- device scratch ----------------
__device__ float2 g_Fd[MODES * 64];    // e^{-d r}  * (sin, cos)(w r)
__device__ float2 g_Cd[MODES * NC];    // e^{-d 64c}* (sin, cos)(w 64c)
__device__ float2 g_Fg[MODES * 64];    // e^{+d r}  * (sin, cos)
__device__ float2 g_Cg[MODES * 64];    // e^{+d 64c}* (sin, cos)
__device__ float  g_ampT[MODES * AUD];
__device__ float2 g_dots[8][MODES * AUD];   // RAW amp-scaled lag-chunk dots
__device__ float  g_dpart[AUD * F];
__device__ unsigned g_count = 0;
__device__ unsigned g_gen   = 0;

__device__ __forceinline__ void grid_bar()
{
    __threadfence();
    __syncthreads();
    if (threadIdx.x == 0) {
        unsigned gen = *(volatile unsigned*)&g_gen;
        __threadfence();
        if (atomicAdd(&g_count, 1u) == NB - 1) {
            g_count = 0;
            __threadfence();
            *(volatile unsigned*)&g_gen = gen + 1;
        } else {
            while (*(volatile unsigned*)&g_gen == gen) { }
        }
        __threadfence();
    }
    __syncthreads();
}

#define PIDX(q) ((q) + ((q) >> 2))

__global__ void __launch_bounds__(NT) k_all(const float* __restrict__ freq_linear,
                                            const float* __restrict__ amp_value,
                                            const float* __restrict__ alpha_params,
                                            const float* __restrict__ beta_params,
                                            const float* __restrict__ forces,
                                            float* __restrict__ out)
{
    __shared__ __align__(16) u64 smu[4224];   // 33.8KB, re-carved per phase
    float* sm = (float*)smu;
    int b = blockIdx.x, tid = threadIdx.x;

    // ================= Phase A: 2 blocks per mode =================
    {
        int m = b & 63, half = b >> 6;
        float* s_a  = sm;        float* s_aw = sm + 64;
        float* s_b  = sm + 128;  float* s_bw = sm + 192;

        const float la0 = logf(0.6f), la1 = logf(60.0f);
        const float lb0 = logf(2e-8f), lb1 = logf(2e-6f);

        if (tid < 64) {
            float frac = (float)tid / 63.0f;
            float va = expf(la0 + (la1 - la0) * frac);
            float vb = expf(lb0 + (lb1 - lb0) * frac);
            float spa = log1pf(expf(alpha_params[m * 64 + tid]));
            float spb = log1pf(expf(beta_params [m * 64 + tid]));
            s_a[tid] = spa * va; s_aw[tid] = spa;
            s_b[tid] = spb * vb; s_bw[tid] = spb;
        } else if (half == 0 && tid < 80) {
            int a = tid - 64;
            float x = amp_value[a * MODES + m];
            float s = 1.0f / (1.0f + expf(-x));
            g_ampT[m * AUD + a] = 2.0f * expf(2.30258509299404568f * logf(s)) + 1e-7f;
        }
        __syncthreads();
        if (tid < 32) {
            float A  = s_a[tid]  + s_a[tid + 32];
            float AW = s_aw[tid] + s_aw[tid + 32];
            float Bv = s_b[tid]  + s_b[tid + 32];
            float BW = s_bw[tid] + s_bw[tid + 32];
            #pragma unroll
            for (int o = 16; o; o >>= 1) {
                A  += __shfl_xor_sync(0xffffffffu, A, o);
                AW += __shfl_xor_sync(0xffffffffu, AW, o);
                Bv += __shfl_xor_sync(0xffffffffu, Bv, o);
                BW += __shfl_xor_sync(0xffffffffu, BW, o);
            }
            if (tid == 0) {
                float alpha = A / AW, beta = Bv / BW;
                float f2pi = freq_linear[m] * 6.28318530717958647692f;
                float lbd  = f2pi * f2pi;
                float dr   = 0.5f * (alpha + beta * lbd);
                sm[256] = dr / 16000.0f;
                sm[257] = sqrtf(lbd - dr * dr) / 16000.0f;
            }
        }
        __syncthreads();
        float d = sm[256], w = sm[257];
        if (half == 0) {
            if (tid < 257) {
                float n = (float)(tid << 6);
                float s, c;
                sincosf(w * n, &s, &c);
                float Ec = expf(-d * n);
                g_Cd[m * NC + tid] = make_float2(Ec * s, Ec * c);
            }
            if (tid < 64) {
                float nf = (float)tid;
                float s, c;
                sincosf(w * nf, &s, &c);
                float Ef = expf(-d * nf), Ep = expf(d * nf);
                g_Fd[m * 64 + tid] = make_float2(Ef * s, Ef * c);
                g_Fg[m * 64 + tid] = make_float2(Ep * s, Ep * c);
                float nc2 = (float)(tid << 6);
                float s2, c2;
                sincosf(w * nc2, &s2, &c2);
                float Ecp = expf(d * nc2);
                g_Cg[m * 64 + tid] = make_float2(Ecp * s2, Ecp * c2);
            }
        } else {
            if (tid < 256) {
                int i = 257 + tid;
                float n = (float)(i << 6);
                float s, c;
                sincosf(w * n, &s, &c);
                float Ec = expf(-d * n);
                g_Cd[m * NC + i] = make_float2(Ec * s, Ec * c);
            }
        }
    }

    grid_bar();

    // ================= Phase B =================
    if (b < 64) {
        // ---- diagonal pair (ti = b>>3, audio pair p = b&7), register-tiled conv ----
        int ti = b >> 3, p = b & 7;
        int a0 = 2 * p, a1 = a0 + 1;
        u64* sfr2 = smu;               // [0..511]
        u64* sp2p = smu + 512;         // padded logical 1024 -> phys 1280
        u64* sam2 = smu + 1792;        // 64
        u64* spb  = smu + 1856;        // 512 (s0 half combine)
        int fb = 3584 - (ti << 9);

        // zero padded s0 buffer
        sp2p[tid] = 0ull;
        if (tid < 256) sp2p[1024 + tid] = 0ull;
        if (tid < 512) {
            sfr2[tid] = pack2(forces[a0 * F + fb + tid], forces[a1 * F + fb + tid]);
        } else if (tid < 576) {
            int i = tid - 512;
            sam2[i] = pack2(g_ampT[i * AUD + a0], g_ampT[i * AUD + a1]);
        }
        __syncthreads();

        // s0: mode-split halves
        {
            int j = tid & 511;
            int mlo = (tid >> 9) << 5;        // 0 or 32
            int n = j + 1, c2 = n >> 6, r2 = n & 63;
            u64 v2 = 0ull;
            #pragma unroll 4
            for (int mm = 0; mm < 32; mm++) {
                int m = mlo + mm;
                float2 Fd = g_Fd[m * 64 + r2];
                float2 Cd = g_Cd[m * NC + c2];
                float ps = Cd.x * Fd.y + Cd.y * Fd.x;
                v2 = fma2(pack2(ps, ps), sam2[m], v2);
            }
            if (tid >= 512) spb[j] = v2;
            __syncthreads();
            if (tid < 512) {
                int q = 511 + j;
                sp2p[PIDX(q)] = add2(v2, spb[j]);
            }
        }
        __syncthreads();

        // conv: 128 output-quads x 8 tap-eighths, sliding 4-window
        u64 c0a, c1a, c2a, c3a;
        {
            int uq = tid & 127, te = tid >> 7;
            int base = (uq << 2) + (te << 6);
            u64 s0r = sp2p[PIDX(base)];
            u64 s1r = sp2p[PIDX(base + 1)];
            u64 s2r = sp2p[PIDX(base + 2)];
            u64 s3r = sp2p[PIDX(base + 3)];
            c0a = 0ull; c1a = 0ull; c2a = 0ull; c3a = 0ull;
            int kb = te << 6;
            #pragma unroll 4
            for (int kk = 0; kk < 64; kk++) {
                u64 f = sfr2[kb + kk];
                c0a = fma2(f, s0r, c0a);
                c1a = fma2(f, s1r, c1a);
                c2a = fma2(f, s2r, c2a);
                c3a = fma2(f, s3r, c3a);
                s0r = s1r; s1r = s2r; s2r = s3r;
                int q = base + kk + 4;
                s3r = sp2p[q + (q >> 2)];
            }
        }
        __syncthreads();
        // partials into smem (reuse everything), then reduce over tap-eighths
        {
            u64* part = smu;               // 4096 u64
            u64* pp = part + tid * 4;
            pp[0] = c0a; pp[1] = c1a; pp[2] = c2a; pp[3] = c3a;
            __syncthreads();
            if (tid < 512) {
                u64 acc = part[tid];       // te = 0: (0*128+uq)*4+j = tid
                #pragma unroll
                for (int te = 1; te < 8; te++)
                    acc = add2(acc, part[te * 512 + tid]);
                float2 r = unpack2(acc);
                int t0 = (ti << 9) + tid;
                g_dpart[a0 * F + t0] = r.x;
                g_dpart[a1 * F + t0] = r.y;
            }
        }
    } else {
        // ---- one mode per block: ALL 128 (audio x chunk) dot units concurrently ----
        int m = b - 64;
        u64* sR = smu;                 // 4096 taps of (rc, rs)
        int wid = tid >> 5, lane = tid & 31;
        int a = wid >> 1, h = wid & 1;     // warp owns audio a, chunks 4h..4h+3
        float am = g_ampT[m * AUD + a];

        for (int i = tid; i < 4096; i += NT) {
            float2 Fg = g_Fg[m * 64 + (i & 63)];
            float2 Cg = g_Cg[m * 64 + (i >> 6)];
            sR[i] = pack2(Cg.y * Fg.y - Cg.x * Fg.x,
                          Cg.x * Fg.y + Cg.y * Fg.x);
        }
        __syncthreads();

        const float* fp = forces + a * F + 4095;   // g[tau] = fp[-tau]
        u64 acc0 = 0ull, acc1 = 0ull, acc2 = 0ull, acc3 = 0ull;
        int kb = (h << 2) << 9;                    // chunk base: 0 or 2048
        #pragma unroll 4
        for (int s = 0; s < 16; s++) {
            int k = kb + lane + (s << 5);
            float f0 = fp[-k];
            float f1 = fp[-(k + 512)];
            float f2 = fp[-(k + 1024)];
            float f3 = fp[-(k + 1536)];
            acc0 = fma2(pack2(f0, f0), sR[k],        acc0);
            acc1 = fma2(pack2(f1, f1), sR[k + 512],  acc1);
            acc2 = fma2(pack2(f2, f2), sR[k + 1024], acc2);
            acc3 = fma2(pack2(f3, f3), sR[k + 1536], acc3);
        }
        float2 d0 = unpack2(acc0), d1 = unpack2(acc1), d2 = unpack2(acc2), d3 = unpack2(acc3);
        #pragma unroll
        for (int o = 16; o; o >>= 1) {
            d0.x += __shfl_xor_sync(0xffffffffu, d0.x, o);
            d0.y += __shfl_xor_sync(0xffffffffu, d0.y, o);
            d1.x += __shfl_xor_sync(0xffffffffu, d1.x, o);
            d1.y += __shfl_xor_sync(0xffffffffu, d1.y, o);
            d2.x += __shfl_xor_sync(0xffffffffu, d2.x, o);
            d2.y += __shfl_xor_sync(0xffffffffu, d2.y, o);
            d3.x += __shfl_xor_sync(0xffffffffu, d3.x, o);
            d3.y += __shfl_xor_sync(0xffffffffu, d3.y, o);
        }
        if (lane == 0) {
            int cb = h << 2;
            g_dots[cb + 0][m * AUD + a] = make_float2(am * d0.x, am * d0.y);
            g_dots[cb + 1][m * AUD + a] = make_float2(am * d1.x, am * d1.y);
            g_dots[cb + 2][m * AUD + a] = make_float2(am * d2.x, am * d2.y);
            g_dots[cb + 3][m * AUD + a] = make_float2(am * d3.x, am * d3.y);
        }
    }

    grid_bar();

    // ================= Phase C: 256-sample tile, 4 groups (2 audio x 2 mode halves) =================
    {
        int tile = b;
        int tl = tid & 255, g = tid >> 8;
        int ag = g & 1, mg = g >> 1;
        int t = tile * 256 + tl;
        int cc = tile >> 1; if (cc > 8) cc = 8;

        u64*    sA   = smu;                     // 512
        u64*    sB   = sA + 512;                // 512
        float2* sCd  = (float2*)(sA + 1024);    // 320
        u64*    comb = sA + 1344;               // 2048

        u64 acc2[4] = {0ull, 0ull, 0ull, 0ull};

        if (cc > 0) {
            int c2base = (tile * 256 + 1) >> 6;
            if (tid < 512) {
                int mm = tid >> 3, aa = tid & 7;
                int i0 = mm * AUD + 2 * aa;
                float Ae = 0.f, Be = 0.f, Ao = 0.f, Bo = 0.f;
                for (int c = 0; c < cc; c++) {
                    float2 p0 = g_dots[c][i0];
                    float2 p1 = g_dots[c][i0 + 1];
                    Ae += p0.x; Be += p0.y;
                    Ao += p1.x; Bo += p1.y;
                }
                sA[tid] = pack2(Ae, Ao);
                sB[tid] = pack2(Be, Bo);
            } else if (tid < 832) {
                int idx = tid - 512;
                int mm = idx / 5, dc = idx % 5;
                sCd[mm * 5 + dc] = g_Cd[mm * NC + c2base + dc];
            }
            __syncthreads();

            int n = t + 1, dc = (n >> 6) - c2base, r2 = n & 63;
            int mbase = mg << 5;
            #pragma unroll 4
            for (int mm = 0; mm < 32; mm++) {
                int m = mbase + mm;
                float2 Fd = g_Fd[m * 64 + r2];
                float2 Cd = sCd[m * 5 + dc];
                float ps  = Cd.x * Fd.y + Cd.y * Fd.x;
                float npc = Cd.x * Fd.x - Cd.y * Fd.y;
                u64 ps2  = pack2(ps, ps);
                u64 npc2 = pack2(npc, npc);
                const ulonglong2* pAv = (const ulonglong2*)(sA + m * 8 + ag * 4);
                const ulonglong2* pBv = (const ulonglong2*)(sB + m * 8 + ag * 4);
                ulonglong2 va0 = pAv[0], vb0 = pBv[0];
                ulonglong2 va1 = pAv[1], vb1 = pBv[1];
                acc2[0] = fma2(ps2, va0.x, fma2(npc2, vb0.x, acc2[0]));
                acc2[1] = fma2(ps2, va0.y, fma2(npc2, vb0.y, acc2[1]));
                acc2[2] = fma2(ps2, va1.x, fma2(npc2, vb1.x, acc2[2]));
                acc2[3] = fma2(ps2, va1.y, fma2(npc2, vb1.y, acc2[3]));
            }
        }
        __syncthreads();
        if (mg == 1) {
            u64* cp = comb + ((ag << 8) + tl) * 4;
            cp[0] = acc2[0]; cp[1] = acc2[1]; cp[2] = acc2[2]; cp[3] = acc2[3];
        }
        __syncthreads();
        if (mg == 0) {
            u64* cp = comb + ((ag << 8) + tl) * 4;
            float o[8];
            #pragma unroll
            for (int j = 0; j < 4; j++) {
                float2 v = unpack2(add2(acc2[j], cp[j]));
                o[2 * j] = v.x; o[2 * j + 1] = v.y;
            }
            int abase = ag << 3;
            if (t < F) {
                #pragma unroll
                for (int j = 0; j < 8; j++)
                    o[j] += g_dpart[(abase + j) * F + t];
            }
            #pragma unroll
            for (int j = 0; j < 8; j++)
                out[(abase + j) * T + t] = o[j];
        }
    }
}

// ---------------- launch ----------------
extern "C" void kernel_launch(void* const* d_in, const int* in_sizes, int n_in,
                              void* d_out, int out_size)
{
    const float* freq   = (const float*)d_in[0];
    const float* ampv   = (const float*)d_in[1];
    const float* ap     = (const float*)d_in[2];
    const float* bp     = (const float*)d_in[3];
    const float* forces = (const float*)d_in[4];
    float* out = (float*)d_out;

    k_all<<<NB, NT>>>(freq, ampv, ap, bp, forces, out);
}